// round 2
// baseline (speedup 1.0000x reference)
#include <cuda_runtime.h>
#include <cuda_bf16.h>
#include <math.h>

// Problem constants
#define BATCH   2
#define SEQLEN  2048
#define DMODEL  2048
#define NHEADS  16
#define DHEAD   128
#define MTOT    (BATCH * SEQLEN)      // 4096
#define NEG_BIG (-1e30f)

// Scratch (device globals: allocation-free rule).
// NOTE: these are ONLY referenced from device code — taking their address in
// host code yields the host shadow symbol (the R1 bug).
__device__ float g_q[(size_t)MTOT * DMODEL];
__device__ float g_k[(size_t)MTOT * DMODEL];
__device__ float g_v[(size_t)MTOT * DMODEL];
__device__ float g_z[(size_t)MTOT * DMODEL];

// ---------------------------------------------------------------------------
// Kernel 1: fused QKV projection.
// grid = (M/128, NHEADS, 3), block = 256.
// out[m, h*128+col] = sum_k x[m,k] * W[h][k][col] + bias[h][col]
// Classic 128x128x8 register-blocked SGEMM (8x8 per thread).
// ---------------------------------------------------------------------------
__global__ void __launch_bounds__(256) qkv_gemm_kernel(
    const float* __restrict__ x,
    const float* __restrict__ Wq, const float* __restrict__ Wk, const float* __restrict__ Wv,
    const float* __restrict__ bQ, const float* __restrict__ bK, const float* __restrict__ bV)
{
    const int mBase = blockIdx.x * 128;
    const int h     = blockIdx.y;
    const int which = blockIdx.z;

    const float* W    = (which == 0) ? Wq : (which == 1) ? Wk : Wv;
    const float* bias = (which == 0) ? bQ : (which == 1) ? bK : bV;
    float* out        = (which == 0) ? g_q : (which == 1) ? g_k : g_v;

    const float* Wh = W + (size_t)h * DMODEL * DHEAD;   // [2048,128] row-major

    __shared__ float As[8][128];   // transposed A: As[k][m]
    __shared__ float Bs[8][132];   // B tile (row pad)

    const int tid = threadIdx.x;
    const int tx = tid & 15;       // col block (tx*8)
    const int ty = tid >> 4;       // row block (ty*8)

    const int arow = tid >> 1;            // 0..127
    const int ac4  = (tid & 1) * 4;       // 0 or 4
    const int brow = tid >> 5;            // 0..7
    const int bcol = (tid & 31) * 4;      // 0..124

    float acc[8][8];
#pragma unroll
    for (int i = 0; i < 8; i++)
#pragma unroll
        for (int j = 0; j < 8; j++) acc[i][j] = 0.f;

    for (int k0 = 0; k0 < DMODEL; k0 += 8) {
        float4 aval = *(const float4*)&x[(size_t)(mBase + arow) * DMODEL + k0 + ac4];
        float4 bval = *(const float4*)&Wh[(size_t)(k0 + brow) * DHEAD + bcol];
        __syncthreads();   // previous compute done before overwrite
        As[ac4 + 0][arow] = aval.x;
        As[ac4 + 1][arow] = aval.y;
        As[ac4 + 2][arow] = aval.z;
        As[ac4 + 3][arow] = aval.w;
        *(float4*)&Bs[brow][bcol] = bval;
        __syncthreads();

#pragma unroll
        for (int kk = 0; kk < 8; kk++) {
            float av[8], bv[8];
            *(float4*)&av[0] = *(const float4*)&As[kk][ty * 8];
            *(float4*)&av[4] = *(const float4*)&As[kk][ty * 8 + 4];
            *(float4*)&bv[0] = *(const float4*)&Bs[kk][tx * 8];
            *(float4*)&bv[4] = *(const float4*)&Bs[kk][tx * 8 + 4];
#pragma unroll
            for (int i = 0; i < 8; i++)
#pragma unroll
                for (int j = 0; j < 8; j++)
                    acc[i][j] = fmaf(av[i], bv[j], acc[i][j]);
        }
    }

#pragma unroll
    for (int i = 0; i < 8; i++) {
        const size_t row = (size_t)(mBase + ty * 8 + i);
#pragma unroll
        for (int j = 0; j < 8; j++) {
            const int col = tx * 8 + j;
            out[row * DMODEL + h * DHEAD + col] = acc[i][j] + bias[h * DHEAD + col];
        }
    }
}

// ---------------------------------------------------------------------------
// Kernel 2: fused causal attention (flash-style, fp32).
// grid = (SEQLEN/64, NHEADS, BATCH), block = 256 threads.
// Reads g_q/g_k/g_v and writes g_z as device symbols (no host pointers).
// ---------------------------------------------------------------------------
#define QPAD 132   // row stride for 128-wide fp32 tiles (16B aligned)
#define PPAD 68    // row stride for the 64-wide P tile

__global__ void __launch_bounds__(256) attn_kernel()
{
    const int qt = blockIdx.x;
    const int h  = blockIdx.y;
    const int b  = blockIdx.z;
    const int qBase = qt * 64;

    extern __shared__ float sm[];
    float* Qs  = sm;                        // [64][QPAD]
    float* Ks  = Qs + 64 * QPAD;            // [64][QPAD]
    float* Vs  = Ks + 64 * QPAD;            // [64][QPAD]
    float* Ps  = Vs + 64 * QPAD;            // [64][PPAD]
    float* Red = Ps + 64 * PPAD;            // [64][16]

    const int tid = threadIdx.x;
    const int tx = tid & 15;
    const int ty = tid >> 4;

    const float scale = 0.08838834764831845f;  // 1/sqrt(128)

    // Load Q tile
    {
        const size_t baseQ = ((size_t)(b * SEQLEN + qBase) * NHEADS + h) * DHEAD;
        for (int i = tid; i < 64 * 32; i += 256) {
            int r = i >> 5, c4 = (i & 31) << 2;
            *(float4*)&Qs[r * QPAD + c4] =
                *(const float4*)&g_q[baseQ + (size_t)r * NHEADS * DHEAD + c4];
        }
    }

    float m_i[4], l_i[4], o[4][8];
#pragma unroll
    for (int i = 0; i < 4; i++) {
        m_i[i] = NEG_BIG; l_i[i] = 0.f;
#pragma unroll
        for (int j = 0; j < 8; j++) o[i][j] = 0.f;
    }

    const int nkt = qt + 1;   // causal: key tiles 0..qt
    for (int kt = 0; kt < nkt; kt++) {
        const int kBase = kt * 64;
        __syncthreads();   // previous iteration reads done; also orders Q load
        {
            const size_t baseK = ((size_t)(b * SEQLEN + kBase) * NHEADS + h) * DHEAD;
            for (int i = tid; i < 64 * 32; i += 256) {
                int r = i >> 5, c4 = (i & 31) << 2;
                size_t g = baseK + (size_t)r * NHEADS * DHEAD + c4;
                *(float4*)&Ks[r * QPAD + c4] = *(const float4*)&g_k[g];
                *(float4*)&Vs[r * QPAD + c4] = *(const float4*)&g_v[g];
            }
        }
        __syncthreads();

        // S = Q K^T
        float s[4][4];
#pragma unroll
        for (int i = 0; i < 4; i++)
#pragma unroll
            for (int j = 0; j < 4; j++) s[i][j] = 0.f;

#pragma unroll 4
        for (int e4 = 0; e4 < 32; e4++) {
            float4 a[4], bb[4];
#pragma unroll
            for (int i = 0; i < 4; i++)
                a[i] = *(const float4*)&Qs[(i * 16 + ty) * QPAD + e4 * 4];
#pragma unroll
            for (int j = 0; j < 4; j++)
                bb[j] = *(const float4*)&Ks[(j * 16 + tx) * QPAD + e4 * 4];
#pragma unroll
            for (int i = 0; i < 4; i++)
#pragma unroll
                for (int j = 0; j < 4; j++) {
                    s[i][j] = fmaf(a[i].x, bb[j].x, s[i][j]);
                    s[i][j] = fmaf(a[i].y, bb[j].y, s[i][j]);
                    s[i][j] = fmaf(a[i].z, bb[j].z, s[i][j]);
                    s[i][j] = fmaf(a[i].w, bb[j].w, s[i][j]);
                }
        }

        // scale + causal mask
#pragma unroll
        for (int i = 0; i < 4; i++) {
            const int qi = qBase + i * 16 + ty;
#pragma unroll
            for (int j = 0; j < 4; j++) {
                const int ki = kBase + j * 16 + tx;
                s[i][j] = (ki <= qi) ? s[i][j] * scale : NEG_BIG;
            }
        }

        // row max (across the 16 tx slots sharing a row)
#pragma unroll
        for (int i = 0; i < 4; i++) {
            float mm = s[i][0];
#pragma unroll
            for (int j = 1; j < 4; j++) mm = fmaxf(mm, s[i][j]);
            Red[(i * 16 + ty) * 16 + tx] = mm;
        }
        __syncthreads();

        float mnew[4], alpha[4];
#pragma unroll
        for (int i = 0; i < 4; i++) {
            float mm = m_i[i];
            const int r = (i * 16 + ty) * 16;
#pragma unroll
            for (int t = 0; t < 16; t++) mm = fmaxf(mm, Red[r + t]);
            mnew[i] = mm;
            alpha[i] = __expf(m_i[i] - mm);   // m_i=NEG_BIG on first tile -> 0
            m_i[i] = mm;
        }

        // p = exp(s - mnew), local row sums
        float p[4][4], ls[4];
#pragma unroll
        for (int i = 0; i < 4; i++) {
            float ssum = 0.f;
#pragma unroll
            for (int j = 0; j < 4; j++) {
                float pv = __expf(s[i][j] - mnew[i]);
                p[i][j] = pv;
                ssum += pv;
            }
            ls[i] = ssum;
        }
        __syncthreads();  // Red max reads done before sum writes
#pragma unroll
        for (int i = 0; i < 4; i++) {
            Red[(i * 16 + ty) * 16 + tx] = ls[i];
#pragma unroll
            for (int j = 0; j < 4; j++)
                Ps[(i * 16 + ty) * PPAD + (j * 16 + tx)] = p[i][j];
        }
        __syncthreads();

#pragma unroll
        for (int i = 0; i < 4; i++) {
            float ssum = 0.f;
            const int r = (i * 16 + ty) * 16;
#pragma unroll
            for (int t = 0; t < 16; t++) ssum += Red[r + t];
            l_i[i] = l_i[i] * alpha[i] + ssum;
#pragma unroll
            for (int j = 0; j < 8; j++) o[i][j] *= alpha[i];
        }

        // O += P V
#pragma unroll 4
        for (int jj = 0; jj < 64; jj++) {
            float pa[4], vb[8];
#pragma unroll
            for (int i = 0; i < 4; i++)
                pa[i] = Ps[(i * 16 + ty) * PPAD + jj];
#pragma unroll
            for (int j = 0; j < 8; j++)
                vb[j] = Vs[jj * QPAD + j * 16 + tx];
#pragma unroll
            for (int i = 0; i < 4; i++)
#pragma unroll
                for (int j = 0; j < 8; j++)
                    o[i][j] = fmaf(pa[i], vb[j], o[i][j]);
        }
    }

    // normalize + write z[b, q, h, :]
#pragma unroll
    for (int i = 0; i < 4; i++) {
        const size_t row = (size_t)(b * SEQLEN + qBase + i * 16 + ty);
        const float inv = 1.f / l_i[i];
#pragma unroll
        for (int j = 0; j < 8; j++)
            g_z[(row * NHEADS + h) * DHEAD + j * 16 + tx] = o[i][j] * inv;
    }
}

// ---------------------------------------------------------------------------
// Kernel 3: output projection. out[m,n] = sum_k z[m,k]*W_O[k,n] + b_O[n]
// W_O [NHEADS, DHEAD, DMODEL] is contiguously [2048, 2048] row-major.
// grid = (M/128, DMODEL/128), block = 256.
// ---------------------------------------------------------------------------
__global__ void __launch_bounds__(256) out_gemm_kernel(
    const float* __restrict__ Wo, const float* __restrict__ bO,
    float* __restrict__ out)
{
    const int mBase = blockIdx.x * 128;
    const int nBase = blockIdx.y * 128;

    __shared__ float As[8][128];
    __shared__ float Bs[8][132];

    const int tid = threadIdx.x;
    const int tx = tid & 15;
    const int ty = tid >> 4;

    const int arow = tid >> 1;
    const int ac4  = (tid & 1) * 4;
    const int brow = tid >> 5;
    const int bcol = (tid & 31) * 4;

    float acc[8][8];
#pragma unroll
    for (int i = 0; i < 8; i++)
#pragma unroll
        for (int j = 0; j < 8; j++) acc[i][j] = 0.f;

    for (int k0 = 0; k0 < DMODEL; k0 += 8) {
        float4 aval = *(const float4*)&g_z[(size_t)(mBase + arow) * DMODEL + k0 + ac4];
        float4 bval = *(const float4*)&Wo[(size_t)(k0 + brow) * DMODEL + nBase + bcol];
        __syncthreads();
        As[ac4 + 0][arow] = aval.x;
        As[ac4 + 1][arow] = aval.y;
        As[ac4 + 2][arow] = aval.z;
        As[ac4 + 3][arow] = aval.w;
        *(float4*)&Bs[brow][bcol] = bval;
        __syncthreads();

#pragma unroll
        for (int kk = 0; kk < 8; kk++) {
            float av[8], bv[8];
            *(float4*)&av[0] = *(const float4*)&As[kk][ty * 8];
            *(float4*)&av[4] = *(const float4*)&As[kk][ty * 8 + 4];
            *(float4*)&bv[0] = *(const float4*)&Bs[kk][tx * 8];
            *(float4*)&bv[4] = *(const float4*)&Bs[kk][tx * 8 + 4];
#pragma unroll
            for (int i = 0; i < 8; i++)
#pragma unroll
                for (int j = 0; j < 8; j++)
                    acc[i][j] = fmaf(av[i], bv[j], acc[i][j]);
        }
    }

#pragma unroll
    for (int i = 0; i < 8; i++) {
        const size_t row = (size_t)(mBase + ty * 8 + i);
#pragma unroll
        for (int j = 0; j < 8; j++) {
            const int col = nBase + tx * 8 + j;
            out[row * DMODEL + col] = acc[i][j] + bO[col];
        }
    }
}

// ---------------------------------------------------------------------------
// Launch
// ---------------------------------------------------------------------------
extern "C" void kernel_launch(void* const* d_in, const int* in_sizes, int n_in,
                              void* d_out, int out_size)
{
    const float* x  = (const float*)d_in[0];
    const float* Wq = (const float*)d_in[1];
    const float* Wk = (const float*)d_in[2];
    const float* Wv = (const float*)d_in[3];
    const float* Wo = (const float*)d_in[4];
    const float* bQ = (const float*)d_in[5];
    const float* bK = (const float*)d_in[6];
    const float* bV = (const float*)d_in[7];
    const float* bO = (const float*)d_in[8];
    float* out = (float*)d_out;

    // 1) QKV projections
    qkv_gemm_kernel<<<dim3(MTOT / 128, NHEADS, 3), 256>>>(x, Wq, Wk, Wv, bQ, bK, bV);

    // 2) fused causal attention
    const int smem_bytes = (3 * 64 * QPAD + 64 * PPAD + 64 * 16) * (int)sizeof(float);
    static bool attr_set = false;
    if (!attr_set) {
        cudaFuncSetAttribute(attn_kernel, cudaFuncAttributeMaxDynamicSharedMemorySize, smem_bytes);
        attr_set = true;
    }
    attn_kernel<<<dim3(SEQLEN / 64, NHEADS, BATCH), 256, smem_bytes>>>();

    // 3) output projection
    out_gemm_kernel<<<dim3(MTOT / 128, DMODEL / 128), 256>>>(Wo, bO, out);

    (void)in_sizes; (void)n_in; (void)out_size;
}